// round 17
// baseline (speedup 1.0000x reference)
#include <cuda_runtime.h>
#include <cstdint>

#define BATCH 8
#define NPTS 2048
#define BN_TOT (BATCH * NPTS)          // 16384
#define KNN 20
#define M_EDGES (BN_TOT * KNN)         // 327680
#define LDCAT 512
#define FIN_O 1024
#define MAXBLK 4096

typedef unsigned long long ull;

// ---------------- scratch (device globals; no allocations allowed) -------------
__device__ float  g_dist[(size_t)BATCH * NPTS * NPTS];   // 134MB
__device__ int    g_idx [M_EDGES];
__device__ float  g_pmax[(size_t)BN_TOT * 256];          // per-(point,chan) max of pre-BN v
__device__ float  g_pmin[(size_t)BN_TOT * 256];          // ... and min (for sc<0)
__device__ float  g_xcat[(size_t)BN_TOT * LDCAT];
__device__ unsigned g_fmax[BATCH * FIN_O];               // encoded col-max for final
__device__ double g_partS[(size_t)MAXBLK * 256];         // per-block stat partials
__device__ double g_partQ[(size_t)MAXBLK * 256];
__device__ float  g_scale[256];
__device__ float  g_shift[256];

__device__ __forceinline__ float neg_inf() { return __int_as_float(0xff800000); }
__device__ __forceinline__ float pos_inf() { return __int_as_float(0x7f800000); }

// order-preserving float<->uint encode (no NaNs in data)
__device__ __forceinline__ unsigned enc_f(float v) {
    unsigned b = __float_as_uint(v);
    return (b & 0x80000000u) ? ~b : (b | 0x80000000u);
}
__device__ __forceinline__ float dec_f(unsigned k) {
    return __uint_as_float((k & 0x80000000u) ? (k ^ 0x80000000u) : ~k);
}

// ---------------- packed fp32x2 helpers (each half = exact IEEE fp32 op) -------
__device__ __forceinline__ ull pack2(float x, float y) {
    ull r; asm("mov.b64 %0, {%1, %2};" : "=l"(r) : "f"(x), "f"(y)); return r;
}
__device__ __forceinline__ void fma2(ull& acc, ull a, ull b) {
    asm("fma.rn.f32x2 %0, %1, %2, %0;" : "+l"(acc) : "l"(a), "l"(b));
}
__device__ __forceinline__ ull sub2(ull a, ull b) {
    ull d; asm("sub.rn.f32x2 %0, %1, %2;" : "=l"(d) : "l"(a), "l"(b)); return d;
}
__device__ __forceinline__ float2 unpack2(ull v) {
    float2 f; asm("mov.b64 {%0, %1}, %2;" : "=f"(f.x), "=f"(f.y) : "l"(v)); return f;
}

__device__ __forceinline__ void load_h4(const float* __restrict__ row, int kk,
                                        int C, bool al, float v[4]) {
    if (al && kk + 3 < C) {
        float4 t = *(const float4*)&row[kk];
        v[0] = t.x; v[1] = t.y; v[2] = t.z; v[3] = t.w;
    } else {
#pragma unroll
        for (int j = 0; j < 4; j++) { int k = kk + j; v[j] = (k < C) ? row[k] : 0.f; }
    }
}

__device__ __forceinline__ void load_edge4(const float* __restrict__ rowN,
                                           const float* __restrict__ rowC,
                                           int kk, int C, int Kd, float v[4]) {
    // all layers here have C,Kd multiples of 16 and aligned rows
    if (kk < C) {
        float4 n = *(const float4*)&rowN[kk];
        float4 c = *(const float4*)&rowC[kk];
        v[0] = n.x - c.x; v[1] = n.y - c.y; v[2] = n.z - c.z; v[3] = n.w - c.w;
    } else {
        float4 c = *(const float4*)&rowC[kk - C];
        v[0] = c.x; v[1] = c.y; v[2] = c.z; v[3] = c.w;
    }
}

// ---------------- pairwise sq distances (UNCHANGED from R16, bitwise) ----------
__global__ __launch_bounds__(256, 2)
void dist_gemm(const float* __restrict__ h, int ld, int C) {
    if (blockIdx.y > blockIdx.x) return;
    __shared__ __align__(16) float As[2][16][132];
    __shared__ __align__(16) float Bs[2][16][132];
    int b   = blockIdx.z;
    const float* hb = h + (size_t)b * NPTS * ld;
    int tid = threadIdx.x;
    int tx = tid & 15, ty = tid >> 4;
    int m0 = blockIdx.y * 128, n0 = blockIdx.x * 128;
    int r  = tid >> 1, ks = (tid & 1) * 8;
    bool al = ((ld & 3) == 0);

    ull acc2[8][4];
#pragma unroll
    for (int i = 0; i < 8; i++)
#pragma unroll
        for (int j = 0; j < 4; j++) acc2[i][j] = 0ull;

    const float* Arow = hb + (size_t)(m0 + r) * ld;
    const float* Brow = hb + (size_t)(n0 + r) * ld;

    int ntiles = (C + 15) / 16;
    float apf[8], bpf[8];
    load_h4(Arow, ks,     C, al, apf);
    load_h4(Arow, ks + 4, C, al, apf + 4);
    load_h4(Brow, ks,     C, al, bpf);
    load_h4(Brow, ks + 4, C, al, bpf + 4);
#pragma unroll
    for (int j = 0; j < 8; j++) { As[0][ks + j][r] = apf[j]; Bs[0][ks + j][r] = bpf[j]; }
    __syncthreads();

    for (int t = 0; t < ntiles; t++) {
        int p = t & 1;
        if (t + 1 < ntiles) {
            int k0 = (t + 1) * 16;
            load_h4(Arow, k0 + ks,     C, al, apf);
            load_h4(Arow, k0 + ks + 4, C, al, apf + 4);
            load_h4(Brow, k0 + ks,     C, al, bpf);
            load_h4(Brow, k0 + ks + 4, C, al, bpf + 4);
        }
#pragma unroll
        for (int k = 0; k < 16; k++) {
            float a[8];
            *(float4*)(a)     = *(const float4*)&As[p][k][ty * 8];
            *(float4*)(a + 4) = *(const float4*)&As[p][k][ty * 8 + 4];
            ull bp[4];
            const ull* bpp = (const ull*)&Bs[p][k][tx * 8];
#pragma unroll
            for (int j = 0; j < 4; j++) bp[j] = bpp[j];
#pragma unroll
            for (int i = 0; i < 8; i++) {
                ull ap = pack2(a[i], a[i]);
#pragma unroll
                for (int j = 0; j < 4; j++) {
                    ull d = sub2(ap, bp[j]);
                    fma2(acc2[i][j], d, d);
                }
            }
        }
        if (t + 1 < ntiles) {
#pragma unroll
            for (int j = 0; j < 8; j++) {
                As[1 - p][ks + j][r] = apf[j];
                Bs[1 - p][ks + j][r] = bpf[j];
            }
            __syncthreads();
        }
    }

    float acc[8][8];
#pragma unroll
    for (int i = 0; i < 8; i++)
#pragma unroll
        for (int j = 0; j < 4; j++) {
            float2 f = unpack2(acc2[i][j]);
            acc[i][2 * j] = f.x; acc[i][2 * j + 1] = f.y;
        }

    float* dbase = g_dist + (size_t)b * NPTS * NPTS;
#pragma unroll
    for (int i = 0; i < 8; i++) {
        float* drow = dbase + (size_t)(m0 + ty * 8 + i) * NPTS;
#pragma unroll
        for (int jj = 0; jj < 2; jj++) {
            float4 v;
            v.x = acc[i][jj * 4 + 0];
            v.y = acc[i][jj * 4 + 1];
            v.z = acc[i][jj * 4 + 2];
            v.w = acc[i][jj * 4 + 3];
            *(float4*)&drow[n0 + tx * 8 + jj * 4] = v;
        }
    }
    if (blockIdx.y != blockIdx.x) {
        __syncthreads();
        float (*Tst)[132] = (float(*)[132])&As[0][0][0];
        for (int c = 0; c < 4; c++) {
            if ((tx >> 2) == c) {
#pragma unroll
                for (int j = 0; j < 8; j++) {
                    int nl = (tx & 3) * 8 + j;
#pragma unroll
                    for (int i = 0; i < 8; i++)
                        Tst[nl][ty * 8 + i] = acc[i][j];
                }
            }
            __syncthreads();
            int nl2 = tid >> 3;
            int mc  = (tid & 7) * 16;
            float* dTrow = dbase + (size_t)(n0 + c * 32 + nl2) * NPTS + m0 + mc;
#pragma unroll
            for (int q = 0; q < 4; q++)
                *(float4*)&dTrow[q * 4] = *(const float4*)&Tst[nl2][mc + q * 4];
            __syncthreads();
        }
    }
}

// ---------------- warp-per-row top-K (UNCHANGED: bitwise-critical) -------------
__global__ void topk_kernel() {
    int gwarp = (blockIdx.x * blockDim.x + threadIdx.x) >> 5;
    int lane  = threadIdx.x & 31;
    if (gwarp >= BN_TOT) return;
    const float* drow = &g_dist[(size_t)gwarp * NPTS];

    float best[KNN];
    int   bidx[KNN];
#pragma unroll
    for (int i = 0; i < KNN; i++) { best[i] = pos_inf(); bidx[i] = -1; }

    for (int m = lane; m < NPTS; m += 32) {
        float d = drow[m];
        if (d < best[KNN - 1]) {
            int p = KNN - 1;
            while (p > 0 && best[p - 1] > d) {
                best[p] = best[p - 1]; bidx[p] = bidx[p - 1]; p--;
            }
            best[p] = d; bidx[p] = m;
        }
    }
    int ptr = 0;
    for (int s = 0; s < KNN; s++) {
        float v  = (ptr < KNN) ? best[ptr] : pos_inf();
        int   ci = (ptr < KNN) ? bidx[ptr] : -1;
        float mv = v; int ml = lane;
#pragma unroll
        for (int off = 16; off > 0; off >>= 1) {
            float ov = __shfl_down_sync(0xffffffffu, mv, off);
            int   ol = __shfl_down_sync(0xffffffffu, ml, off);
            if (ov < mv) { mv = ov; ml = ol; }
        }
        ml = __shfl_sync(0xffffffffu, ml, 0);
        int widx = __shfl_sync(0xffffffffu, ci, ml);
        if (lane == ml) ptr++;
        if (lane == 0) g_idx[gwarp * KNN + s] = widx;
    }
}

// ---------------- layer-1 edge conv: point-owned, direct max/min stores --------
// 1024 blocks x 16 points (320 edges). v = same fmaf chain as before => bitwise.
__global__ __launch_bounds__(256, 4)
void edge1_kernel(const float* __restrict__ h,
                  const float* __restrict__ W,
                  const float* __restrict__ bias) {
    __shared__ float  sW[64][6];
    __shared__ float  sB[64];
    __shared__ float  sE[320][6];
    __shared__ double sPS[4][64];
    __shared__ double sPQ[4][64];
    int tid = threadIdx.x;
    if (tid < 64) sB[tid] = bias[tid];
    for (int i = tid; i < 64 * 6; i += 256) sW[i / 6][i % 6] = W[i];
    for (int e = tid; e < 320; e += 256) {
        int m  = blockIdx.x * 320 + e;
        int bn = m / KNN;
        int b  = bn >> 11;
        int nbr = g_idx[m];
        const float* rc = h + (size_t)bn * 3;
        const float* rn = h + (size_t)((b << 11) + nbr) * 3;
        sE[e][0] = rn[0] - rc[0];
        sE[e][1] = rn[1] - rc[1];
        sE[e][2] = rn[2] - rc[2];
        sE[e][3] = rc[0];
        sE[e][4] = rc[1];
        sE[e][5] = rc[2];
    }
    __syncthreads();

    int o  = tid & 63;
    int pg = tid >> 6;   // 0..3
    float w0 = sW[o][0], w1 = sW[o][1], w2 = sW[o][2];
    float w3 = sW[o][3], w4 = sW[o][4], w5 = sW[o][5];
    float bv = sB[o];
    double ps = 0.0, pq = 0.0;

    for (int p = pg; p < 16; p += 4) {
        float mx = neg_inf(), mn = pos_inf();
#pragma unroll
        for (int k = 0; k < KNN; k++) {
            int e = p * KNN + k;
            float acc = 0.f;
            acc = fmaf(sE[e][0], w0, acc);
            acc = fmaf(sE[e][1], w1, acc);
            acc = fmaf(sE[e][2], w2, acc);
            acc = fmaf(sE[e][3], w3, acc);
            acc = fmaf(sE[e][4], w4, acc);
            acc = fmaf(sE[e][5], w5, acc);
            float v = acc + bv;
            ps += (double)v;
            pq += (double)v * (double)v;
            mx = fmaxf(mx, v);
            mn = fminf(mn, v);
        }
        int pt = blockIdx.x * 16 + p;
        g_pmax[(size_t)pt * 64 + o] = mx;
        g_pmin[(size_t)pt * 64 + o] = mn;
    }
    sPS[pg][o] = ps;
    sPQ[pg][o] = pq;
    __syncthreads();
    if (tid < 64) {
        g_partS[(size_t)blockIdx.x * 256 + tid] =
            sPS[0][tid] + sPS[1][tid] + sPS[2][tid] + sPS[3][tid];
        g_partQ[(size_t)blockIdx.x * 256 + tid] =
            sPQ[0][tid] + sPQ[1][tid] + sPQ[2][tid] + sPQ[3][tid];
    }
}

// ---------------- edge GEMM: M=80 (4 points), 5xTN micro, f32x2 ----------------
// No hpre: emits per-(point,chan) max/min (direct store, block-exclusive) +
// stats partials. k-order of accumulation == R16 => v bitwise identical.
template<int TN>   // 8 -> TILE_N 128; 4 -> 64
__global__ __launch_bounds__(256, 3)
void edge_gemm(const float* __restrict__ h, int ld, int C,
               const float* __restrict__ W,
               const float* __restrict__ bias, int O) {
    const int TILE_N = TN * 16;
    const int Kd = 2 * C;
    __shared__ __align__(16) float As[2][16][84];
    __shared__ __align__(16) float Bs[2][16][TILE_N + 4];

    int tid = threadIdx.x;
    int tx = tid & 15, ty = tid >> 4;
    int m0 = blockIdx.x * 80, n0 = blockIdx.y * TILE_N;

    ull accp[5][TN / 2];
#pragma unroll
    for (int i = 0; i < 5; i++)
#pragma unroll
        for (int j = 0; j < TN / 2; j++) accp[i][j] = 0ull;

    // A loaders: threads 0..159, row = t>>1 (0..79), khalf = (t&1)*8
    bool aload = tid < 160;
    int  arow  = tid >> 1;
    int  aks   = (tid & 1) * 8;
    const float* rowC = h;
    const float* rowN = h;
    if (aload) {
        int m   = m0 + arow;
        int bn  = m / KNN;
        int b   = bn >> 11;
        int nbr = g_idx[m];
        rowC = h + (size_t)bn * ld;
        rowN = h + (size_t)((b << 11) + nbr) * ld;
    }
    // B loaders: threads 0..2*TILE_N-1, col = t>>1, khalf = (t&1)*8
    bool bload = tid < TILE_N * 2;
    int  nw    = tid >> 1;
    int  wk    = (tid & 1) * 8;
    const float* Wrow = W + (size_t)(n0 + (bload ? nw : 0)) * Kd;

    int ntiles = Kd / 16;
    float apf[8], wpf[8];
    if (aload) {
        load_edge4(rowN, rowC, aks,     C, Kd, apf);
        load_edge4(rowN, rowC, aks + 4, C, Kd, apf + 4);
#pragma unroll
        for (int j = 0; j < 8; j++) As[0][aks + j][arow] = apf[j];
    }
    if (bload) {
        *(float4*)wpf       = *(const float4*)&Wrow[wk];
        *(float4*)(wpf + 4) = *(const float4*)&Wrow[wk + 4];
#pragma unroll
        for (int j = 0; j < 8; j++) Bs[0][wk + j][nw] = wpf[j];
    }
    __syncthreads();

    for (int t = 0; t < ntiles; t++) {
        int p = t & 1;
        if (t + 1 < ntiles) {
            int k0 = (t + 1) * 16;
            if (aload) {
                load_edge4(rowN, rowC, k0 + aks,     C, Kd, apf);
                load_edge4(rowN, rowC, k0 + aks + 4, C, Kd, apf + 4);
            }
            if (bload) {
                *(float4*)wpf       = *(const float4*)&Wrow[k0 + wk];
                *(float4*)(wpf + 4) = *(const float4*)&Wrow[k0 + wk + 4];
            }
        }
#pragma unroll
        for (int k = 0; k < 16; k++) {
            float a[5];
#pragma unroll
            for (int i = 0; i < 5; i++) a[i] = As[p][k][ty * 5 + i];
            ull bp[TN / 2];
            const ull* bpp = (const ull*)&Bs[p][k][tx * TN];
#pragma unroll
            for (int j = 0; j < TN / 2; j++) bp[j] = bpp[j];
#pragma unroll
            for (int i = 0; i < 5; i++) {
                ull ap = pack2(a[i], a[i]);
#pragma unroll
                for (int j = 0; j < TN / 2; j++)
                    fma2(accp[i][j], ap, bp[j]);
            }
        }
        if (t + 1 < ntiles) {
            if (aload) {
#pragma unroll
                for (int j = 0; j < 8; j++) As[1 - p][aks + j][arow] = apf[j];
            }
            if (bload) {
#pragma unroll
                for (int j = 0; j < 8; j++) Bs[1 - p][wk + j][nw] = wpf[j];
            }
            __syncthreads();
        }
    }

    float acc[5][TN];
#pragma unroll
    for (int i = 0; i < 5; i++)
#pragma unroll
        for (int j = 0; j < TN / 2; j++) {
            float2 f = unpack2(accp[i][j]);
            acc[i][2 * j] = f.x; acc[i][2 * j + 1] = f.y;
        }

    // ---- epilogue: bias, stats, per-point max/min; smem reused ----
    __syncthreads();
    float*  sM  = (float*)&As[0][0][0];                 // [8][TILE_N] warp max
    float*  sN  = sM + 8 * TILE_N;                      // [8][TILE_N] warp min
    double* sPS = (double*)&Bs[0][0][0];                // [8][TILE_N]
    double* sPQ = sPS + 8 * TILE_N;
    int w = tid >> 5, lane = tid & 31;
#pragma unroll
    for (int j = 0; j < TN; j++) {
        int col = tx * TN + j;
        float bv = bias[n0 + col];
        double ps = 0.0, pq = 0.0;
        float mx = neg_inf(), mn = pos_inf();
#pragma unroll
        for (int i = 0; i < 5; i++) {
            float v = acc[i][j] + bv;
            ps += (double)v;
            pq += (double)v * (double)v;
            mx = fmaxf(mx, v);
            mn = fminf(mn, v);
        }
        ps += __shfl_xor_sync(0xffffffffu, ps, 16);     // combine ty pairs
        pq += __shfl_xor_sync(0xffffffffu, pq, 16);
        mx = fmaxf(mx, __shfl_xor_sync(0xffffffffu, mx, 16));
        mn = fminf(mn, __shfl_xor_sync(0xffffffffu, mn, 16));
        if (lane < 16) {
            sPS[w * TILE_N + col] = ps;
            sPQ[w * TILE_N + col] = pq;
            sM [w * TILE_N + col] = mx;
            sN [w * TILE_N + col] = mn;
        }
    }
    __syncthreads();
    if (tid < TILE_N) {
        double s = 0.0, q = 0.0;
#pragma unroll
        for (int w2 = 0; w2 < 8; w2++) {
            s += sPS[w2 * TILE_N + tid];
            q += sPQ[w2 * TILE_N + tid];
        }
        g_partS[(size_t)blockIdx.x * 256 + n0 + tid] = s;
        g_partQ[(size_t)blockIdx.x * 256 + n0 + tid] = q;
    }
    // per-point max/min: point p rows 20p..20p+19 = warps 2p, 2p+1
    int items = 4 * TILE_N;
    for (int it = tid; it < items; it += 256) {
        int p   = it / TILE_N;
        int col = it % TILE_N;
        float mx = fmaxf(sM[(2 * p) * TILE_N + col], sM[(2 * p + 1) * TILE_N + col]);
        float mn = fminf(sN[(2 * p) * TILE_N + col], sN[(2 * p + 1) * TILE_N + col]);
        int pt = blockIdx.x * 4 + p;
        g_pmax[(size_t)pt * O + n0 + col] = mx;
        g_pmin[(size_t)pt * O + n0 + col] = mn;
    }
}

// ---------------- final conv GEMM fused with max-over-N ------------------------
__global__ __launch_bounds__(256, 2)
void gemm_final(const float* __restrict__ A, int lda,
                const float* __restrict__ W, int ldw,
                const float* __restrict__ bias) {
    __shared__ __align__(16) float As[2][16][132];
    __shared__ __align__(16) float Bs[2][16][132];
    int tid = threadIdx.x;
    int tx = tid & 15, ty = tid >> 4;
    int m0 = blockIdx.x * 128, n0 = blockIdx.y * 128;
    int r  = tid >> 1, ks = (tid & 1) * 8;

    ull accp[8][4];
#pragma unroll
    for (int i = 0; i < 8; i++)
#pragma unroll
        for (int j = 0; j < 4; j++) accp[i][j] = 0ull;

    const float* Arow = A + (size_t)(m0 + r) * lda;
    const float* Wrow = W + (size_t)(n0 + r) * ldw;

    int ntiles = LDCAT / 16;
    float apf[8], wpf[8];
    load_h4(Arow, ks,     LDCAT, true, apf);
    load_h4(Arow, ks + 4, LDCAT, true, apf + 4);
    load_h4(Wrow, ks,     LDCAT, true, wpf);
    load_h4(Wrow, ks + 4, LDCAT, true, wpf + 4);
#pragma unroll
    for (int j = 0; j < 8; j++) { As[0][ks + j][r] = apf[j]; Bs[0][ks + j][r] = wpf[j]; }
    __syncthreads();

    for (int t = 0; t < ntiles; t++) {
        int p = t & 1;
        if (t + 1 < ntiles) {
            int k0 = (t + 1) * 16;
            load_h4(Arow, k0 + ks,     LDCAT, true, apf);
            load_h4(Arow, k0 + ks + 4, LDCAT, true, apf + 4);
            load_h4(Wrow, k0 + ks,     LDCAT, true, wpf);
            load_h4(Wrow, k0 + ks + 4, LDCAT, true, wpf + 4);
        }
#pragma unroll
        for (int k = 0; k < 16; k++) {
            float a[8];
            *(float4*)(a)     = *(const float4*)&As[p][k][ty * 8];
            *(float4*)(a + 4) = *(const float4*)&As[p][k][ty * 8 + 4];
            ull bp[4];
            const ull* bpp = (const ull*)&Bs[p][k][tx * 8];
#pragma unroll
            for (int j = 0; j < 4; j++) bp[j] = bpp[j];
#pragma unroll
            for (int i = 0; i < 8; i++) {
                ull ap = pack2(a[i], a[i]);
#pragma unroll
                for (int j = 0; j < 4; j++)
                    fma2(accp[i][j], ap, bp[j]);
            }
        }
        if (t + 1 < ntiles) {
#pragma unroll
            for (int j = 0; j < 8; j++) {
                As[1 - p][ks + j][r] = apf[j];
                Bs[1 - p][ks + j][r] = wpf[j];
            }
            __syncthreads();
        }
    }

    // epilogue: bias + per-column max over this block's 128 rows -> atomicMax
    __syncthreads();
    float* sM = (float*)&As[0][0][0];   // [8][128]
    int w = tid >> 5, lane = tid & 31;
#pragma unroll
    for (int jp = 0; jp < 4; jp++) {
        float2 f0 = unpack2(accp[0][jp]);
        float2 f1 = unpack2(accp[1][jp]);
        float2 f2 = unpack2(accp[2][jp]);
        float2 f3 = unpack2(accp[3][jp]);
        float2 f4 = unpack2(accp[4][jp]);
        float2 f5 = unpack2(accp[5][jp]);
        float2 f6 = unpack2(accp[6][jp]);
        float2 f7 = unpack2(accp[7][jp]);
#pragma unroll
        for (int half = 0; half < 2; half++) {
            int col = tx * 8 + jp * 2 + half;
            float bv = bias[n0 + col];
            float v0 = (half ? f0.y : f0.x) + bv;
            float v1 = (half ? f1.y : f1.x) + bv;
            float v2 = (half ? f2.y : f2.x) + bv;
            float v3 = (half ? f3.y : f3.x) + bv;
            float v4 = (half ? f4.y : f4.x) + bv;
            float v5 = (half ? f5.y : f5.x) + bv;
            float v6 = (half ? f6.y : f6.x) + bv;
            float v7 = (half ? f7.y : f7.x) + bv;
            float mx = fmaxf(fmaxf(fmaxf(v0, v1), fmaxf(v2, v3)),
                             fmaxf(fmaxf(v4, v5), fmaxf(v6, v7)));
            mx = fmaxf(mx, __shfl_xor_sync(0xffffffffu, mx, 16));
            if (lane < 16) sM[w * 128 + col] = mx;
        }
    }
    __syncthreads();
    if (tid < 128) {
        float mx = sM[tid];
#pragma unroll
        for (int w2 = 1; w2 < 8; w2++) mx = fmaxf(mx, sM[w2 * 128 + tid]);
        int b = m0 >> 11;
        atomicMax(&g_fmax[b * FIN_O + n0 + tid], enc_f(mx));
    }
}

__global__ void init_fmax() {
    int t = blockIdx.x * blockDim.x + threadIdx.x;
    if (t < BATCH * FIN_O) g_fmax[t] = 0u;
}

__global__ void decode_out(float* __restrict__ out) {
    int t = blockIdx.x * blockDim.x + threadIdx.x;
    if (t < BATCH * FIN_O) out[t] = dec_f(g_fmax[t]);
}

// ---------------- stats reduce: one block per output channel -------------------
__global__ void reduce_stats(const float* __restrict__ gam,
                             const float* __restrict__ bet,
                             int nblk, double cnt) {
    __shared__ double ss[256], sq[256];
    int o   = blockIdx.x;
    int tid = threadIdx.x;
    double s = 0.0, q = 0.0;
    for (int bidx = tid; bidx < nblk; bidx += 256) {
        s += g_partS[(size_t)bidx * 256 + o];
        q += g_partQ[(size_t)bidx * 256 + o];
    }
    ss[tid] = s; sq[tid] = q;
    __syncthreads();
    for (int st = 128; st > 0; st >>= 1) {
        if (tid < st) { ss[tid] += ss[tid + st]; sq[tid] += sq[tid + st]; }
        __syncthreads();
    }
    if (tid == 0) {
        double mean = ss[0] / cnt;
        double var  = sq[0] / cnt - mean * mean;
        float inv = rsqrtf((float)var + 1e-5f);
        float sc  = gam[o] * inv;
        g_scale[o] = sc;
        g_shift[o] = bet[o] - (float)mean * sc;
    }
}

// ---------------- BN + LeakyReLU on pre-computed per-point extremum ------------
// monotone fusion: sc>=0 -> use max, sc<0 -> use min (exact)
__global__ void bn_relu_small(int O, int outOff) {
    int t = blockIdx.x * blockDim.x + threadIdx.x;
    if (t >= BN_TOT * O) return;
    int o  = t % O;
    int bn = t / O;
    float sc = g_scale[o], sh = g_shift[o];
    float M = (sc >= 0.f) ? g_pmax[(size_t)bn * O + o] : g_pmin[(size_t)bn * O + o];
    float v = fmaf(M, sc, sh);
    v = (v >= 0.f) ? v : 0.2f * v;
    g_xcat[(size_t)bn * LDCAT + outOff + o] = v;
}

// ==============================================================================
extern "C" void kernel_launch(void* const* d_in, const int* in_sizes, int n_in,
                              void* d_out, int out_size) {
    const float* x = (const float*)d_in[0];
    const float* Wm[4], *bm[4], *gm[4], *bem[4];
    for (int i = 0; i < 4; i++) {
        Wm[i]  = (const float*)d_in[1 + 4 * i];
        bm[i]  = (const float*)d_in[2 + 4 * i];
        gm[i]  = (const float*)d_in[3 + 4 * i];
        bem[i] = (const float*)d_in[4 + 4 * i];
    }
    const float* Wf = (const float*)d_in[17];
    const float* bf = (const float*)d_in[18];
    float* out = (float*)d_out;

    float *xcat_ptr;
    cudaGetSymbolAddress((void**)&xcat_ptr, g_xcat);

    const int Hs[4]   = {64, 64, 128, 256};
    const int offs[4] = {0, 64, 128, 256};

    const float* hsrc = x;
    int ld = 3, C = 3;

    for (int i = 0; i < 4; i++) {
        int O = Hs[i];

        dist_gemm<<<dim3(NPTS / 128, NPTS / 128, BATCH), 256>>>(hsrc, ld, C);
        topk_kernel<<<BN_TOT / 8, 256>>>();

        int nblk;
        if (i == 0) {
            nblk = BN_TOT / 16;                       // 1024
            edge1_kernel<<<nblk, 256>>>(hsrc, Wm[0], bm[0]);
        } else if (O == 64) {
            nblk = M_EDGES / 80;                      // 4096
            edge_gemm<4><<<dim3(nblk, 1), 256>>>(hsrc, ld, C, Wm[i], bm[i], O);
        } else {
            nblk = M_EDGES / 80;                      // 4096
            edge_gemm<8><<<dim3(nblk, O / 128), 256>>>(hsrc, ld, C, Wm[i], bm[i], O);
        }

        reduce_stats<<<O, 256>>>(gm[i], bem[i], nblk, (double)M_EDGES);
        bn_relu_small<<<((size_t)BN_TOT * O + 255) / 256, 256>>>(O, offs[i]);

        hsrc = xcat_ptr + offs[i];
        ld = LDCAT;
        C  = O;
    }

    // final 1x1 conv fused with global max pool over N
    init_fmax<<<(BATCH * FIN_O + 255) / 256, 256>>>();
    gemm_final<<<dim3(BN_TOT / 128, FIN_O / 128), 256>>>(
        xcat_ptr, LDCAT, Wf, LDCAT, bf);
    decode_out<<<(BATCH * FIN_O + 255) / 256, 256>>>(out);
}